// round 11
// baseline (speedup 1.0000x reference)
#include <cuda_runtime.h>
#include <math.h>

// SphereConv: out[2,B,F,L,M] from x[B,1,C,L,M] (complex as 2 arrays) and
// w[F,C,N,1] (complex), weights interp N=64->L=256, channel-mean, sqrt(1+l)
// scale, relu on real part.
//
// R10: max-occupancy probe. FG=4 f-split -> 2 filters/thread, 16 accumulator
// floats, ~40 regs, 256-thread blocks => ~90% theoretical occupancy (vs 40%
// max tried before). x addresses shared by the 4 f-groups hit L1. Keep
// evict_last x loads + evict-first streaming stores. No manual prefetch --
// let warp parallelism cover DRAM latency.
namespace {

constexpr int B = 4, C = 32, L = 256, M = 256, F = 8, N = 64;
constexpr int FG = 4;                // f-groups per block
constexpr int FPT = F / FG;          // filters per thread = 2
constexpr int THREADS = 64 * FG;     // 256
constexpr int CSTRIDE4 = L * M / 4;  // float4 stride between channels

__device__ __forceinline__ unsigned long long mk_persist_policy()
{
    unsigned long long pol;
    asm("createpolicy.fractional.L2::evict_last.b64 %0, 1.0;" : "=l"(pol));
    return pol;
}

__device__ __forceinline__ float4 ldg_persist(const float4* p,
                                              unsigned long long pol)
{
    float4 v;
    asm("ld.global.nc.L2::cache_hint.v4.f32 {%0,%1,%2,%3}, [%4], %5;"
        : "=f"(v.x), "=f"(v.y), "=f"(v.z), "=f"(v.w)
        : "l"(p), "l"(pol));
    return v;
}

__device__ __forceinline__ void stg_stream(float4* p, float4 v)
{
    asm volatile("st.global.cs.v4.f32 [%0], {%1,%2,%3,%4};"
                 :: "l"(p), "f"(v.x), "f"(v.y), "f"(v.z), "f"(v.w)
                 : "memory");
}

__global__ __launch_bounds__(THREADS)
void sphere_conv_kernel(const float* __restrict__ xr,
                        const float* __restrict__ xi,
                        const float* __restrict__ wr,
                        const float* __restrict__ wi,
                        float* __restrict__ out)
{
    const int bl = blockIdx.x;
    const int b  = bl >> 8;        // bl / L
    const int l  = bl & (L - 1);   // bl % L

    // Interpolated weights for this l: [c][f] layout, f fastest.
    __shared__ float swr[C * F];
    __shared__ float swi[C * F];

    const int tid = threadIdx.x;
    const int fg  = tid >> 6;      // f-group (0..3)
    const int m4  = tid & 63;      // float4 index within the M=256 row

    {
        float t  = ((float)l / (float)(L - 1)) * (float)(N - 1);
        int   lo = (int)floorf(t);
        lo = lo < 0 ? 0 : (lo > N - 2 ? N - 2 : lo);
        float frac = t - (float)lo;
        float sc = sqrtf(1.0f + (float)l) * (1.0f / (float)C);
        for (int i = tid; i < C * F; i += THREADS) {
            int c = i >> 3;   // i / F
            int f = i & 7;    // i % F
            int widx = (f * C + c) * N + lo;
            swr[i] = (wr[widx] * (1.0f - frac) + wr[widx + 1] * frac) * sc;
            swi[i] = (wi[widx] * (1.0f - frac) + wi[widx + 1] * frac) * sc;
        }
    }
    __syncthreads();

    const unsigned long long pol = mk_persist_policy();

    const size_t base4 = ((size_t)b * C * L + l) * (M / 4) + m4;
    const float4* xr4 = reinterpret_cast<const float4*>(xr) + base4;
    const float4* xi4 = reinterpret_cast<const float4*>(xi) + base4;

    float4 ar[FPT], ai[FPT];
#pragma unroll
    for (int f = 0; f < FPT; ++f) {
        ar[f] = make_float4(0.f, 0.f, 0.f, 0.f);
        ai[f] = make_float4(0.f, 0.f, 0.f, 0.f);
    }

    // this group's 2 filters at channel c: float2 at [c*4 + fg] (float2 view)
    const float2* swr2 = reinterpret_cast<const float2*>(swr) + fg;
    const float2* swi2 = reinterpret_cast<const float2*>(swi) + fg;

#pragma unroll 4
    for (int c = 0; c < C; ++c) {
        float4 vr = ldg_persist(xr4 + c * CSTRIDE4, pol);
        float4 vi = ldg_persist(xi4 + c * CSTRIDE4, pol);
        float2 w0 = swr2[c * 4];
        float2 u0 = swi2[c * 4];
        float wv[2] = {w0.x, w0.y};
        float uv[2] = {u0.x, u0.y};
#pragma unroll
        for (int f = 0; f < FPT; ++f) {
            float a  = wv[f];
            float bb = uv[f];
            ar[f].x = fmaf(a, vr.x, fmaf(-bb, vi.x, ar[f].x));
            ar[f].y = fmaf(a, vr.y, fmaf(-bb, vi.y, ar[f].y));
            ar[f].z = fmaf(a, vr.z, fmaf(-bb, vi.z, ar[f].z));
            ar[f].w = fmaf(a, vr.w, fmaf(-bb, vi.w, ar[f].w));
            ai[f].x = fmaf(a, vi.x, fmaf( bb, vr.x, ai[f].x));
            ai[f].y = fmaf(a, vi.y, fmaf( bb, vr.y, ai[f].y));
            ai[f].z = fmaf(a, vi.z, fmaf( bb, vr.z, ai[f].z));
            ai[f].w = fmaf(a, vi.w, fmaf( bb, vr.w, ai[f].w));
        }
    }

    // out shape (2, B, F, L, M); relu on real part; streaming stores.
    float4* out4 = reinterpret_cast<float4*>(out);
#pragma unroll
    for (int f = 0; f < FPT; ++f) {
        int fglob = fg * FPT + f;
        float4 r = ar[f];
        r.x = fmaxf(r.x, 0.f);
        r.y = fmaxf(r.y, 0.f);
        r.z = fmaxf(r.z, 0.f);
        r.w = fmaxf(r.w, 0.f);
        size_t or4 = (((size_t)(0 * B + b) * F + fglob) * L + l) * (M / 4) + m4;
        size_t oi4 = (((size_t)(1 * B + b) * F + fglob) * L + l) * (M / 4) + m4;
        stg_stream(out4 + or4, r);
        stg_stream(out4 + oi4, ai[f]);
    }
}

}  // namespace

extern "C" void kernel_launch(void* const* d_in, const int* in_sizes, int n_in,
                              void* d_out, int out_size)
{
    const float* xr = (const float*)d_in[0];
    const float* xi = (const float*)d_in[1];
    const float* wr = (const float*)d_in[2];
    const float* wi = (const float*)d_in[3];
    float* out = (float*)d_out;
    sphere_conv_kernel<<<B * L, THREADS>>>(xr, xi, wr, wi, out);
}

// round 14
// speedup vs baseline: 1.0965x; 1.0965x over previous
#include <cuda_runtime.h>
#include <math.h>

// SphereConv: out[2,B,F,L,M] from x[B,1,C,L,M] (complex as 2 arrays) and
// w[F,C,N,1] (complex), weights interp N=64->L=256, channel-mean, sqrt(1+l)
// scale, relu on real part.
//
// R11: every producer-side knob is flat at ~4TB/s. Test DRAM phase-
// hotspotting: all blocks previously walked c in the same order, so the chip
// hammers one 8MB c-plane at a time. Rotate each block's channel start
// (rot = 5*blockIdx mod 32) so instantaneous traffic spans all of x
// uniformly. Base = best kernel (R6): pair prefetch + evict_last + .cs.
namespace {

constexpr int B = 4, C = 32, L = 256, M = 256, F = 8, N = 64;
constexpr int FG = 2;                // f-groups per block
constexpr int FPT = F / FG;          // filters per thread = 4
constexpr int THREADS = 64 * FG;     // 128
constexpr int CSTRIDE4 = L * M / 4;  // float4 stride between channels

__device__ __forceinline__ unsigned long long mk_persist_policy()
{
    unsigned long long pol;
    asm("createpolicy.fractional.L2::evict_last.b64 %0, 1.0;" : "=l"(pol));
    return pol;
}

__device__ __forceinline__ float4 ldg_persist(const float4* p,
                                              unsigned long long pol)
{
    float4 v;
    asm("ld.global.nc.L2::cache_hint.v4.f32 {%0,%1,%2,%3}, [%4], %5;"
        : "=f"(v.x), "=f"(v.y), "=f"(v.z), "=f"(v.w)
        : "l"(p), "l"(pol));
    return v;
}

__device__ __forceinline__ void stg_stream(float4* p, float4 v)
{
    asm volatile("st.global.cs.v4.f32 [%0], {%1,%2,%3,%4};"
                 :: "l"(p), "f"(v.x), "f"(v.y), "f"(v.z), "f"(v.w)
                 : "memory");
}

__device__ __forceinline__ void cplx_fma(float4& arf, float4& aif,
                                         float a, float bb,
                                         const float4& vr, const float4& vi)
{
    arf.x = fmaf(a, vr.x, fmaf(-bb, vi.x, arf.x));
    arf.y = fmaf(a, vr.y, fmaf(-bb, vi.y, arf.y));
    arf.z = fmaf(a, vr.z, fmaf(-bb, vi.z, arf.z));
    arf.w = fmaf(a, vr.w, fmaf(-bb, vi.w, arf.w));
    aif.x = fmaf(a, vi.x, fmaf( bb, vr.x, aif.x));
    aif.y = fmaf(a, vi.y, fmaf( bb, vr.y, aif.y));
    aif.z = fmaf(a, vi.z, fmaf( bb, vr.z, aif.z));
    aif.w = fmaf(a, vi.w, fmaf( bb, vr.w, aif.w));
}

__global__ __launch_bounds__(THREADS, 6)
void sphere_conv_kernel(const float* __restrict__ xr,
                        const float* __restrict__ xi,
                        const float* __restrict__ wr,
                        const float* __restrict__ wi,
                        float* __restrict__ out)
{
    const int bl = blockIdx.x;
    const int b  = bl >> 8;        // bl / L
    const int l  = bl & (L - 1);   // bl % L
    const int rot = (bl * 5) & (C - 1);   // per-block channel phase offset

    // Interpolated weights for this l, laid out [c][f] so 4 f's load as float4.
    __shared__ float swr[C * F];
    __shared__ float swi[C * F];

    const int tid = threadIdx.x;
    const int fg  = tid >> 6;      // f-group (0/1)
    const int m4  = tid & 63;      // float4 index within the M=256 row

    {
        float t  = ((float)l / (float)(L - 1)) * (float)(N - 1);
        int   lo = (int)floorf(t);
        lo = lo < 0 ? 0 : (lo > N - 2 ? N - 2 : lo);
        float frac = t - (float)lo;
        float sc = sqrtf(1.0f + (float)l) * (1.0f / (float)C);
        for (int i = tid; i < C * F; i += THREADS) {
            int c = i >> 3;   // i / F
            int f = i & 7;    // i % F
            int widx = (f * C + c) * N + lo;
            swr[i] = (wr[widx] * (1.0f - frac) + wr[widx + 1] * frac) * sc;
            swi[i] = (wi[widx] * (1.0f - frac) + wi[widx + 1] * frac) * sc;
        }
    }
    __syncthreads();

    const unsigned long long pol = mk_persist_policy();

    const size_t base4 = ((size_t)b * C * L + l) * (M / 4) + m4;
    const float4* xr4 = reinterpret_cast<const float4*>(xr) + base4;
    const float4* xi4 = reinterpret_cast<const float4*>(xi) + base4;

    float4 ar[FPT], ai[FPT];
#pragma unroll
    for (int f = 0; f < FPT; ++f) {
        ar[f] = make_float4(0.f, 0.f, 0.f, 0.f);
        ai[f] = make_float4(0.f, 0.f, 0.f, 0.f);
    }

    const float4* swr4 = reinterpret_cast<const float4*>(swr) + fg;
    const float4* swi4 = reinterpret_cast<const float4*>(swi) + fg;

    // rotated channel sequence: cc(k) = (k + rot) & 31
    int c0 = rot;
    int c1 = (rot + 1) & (C - 1);
    float4 vr0 = ldg_persist(xr4 + c0 * CSTRIDE4, pol);
    float4 vi0 = ldg_persist(xi4 + c0 * CSTRIDE4, pol);
    float4 vr1 = ldg_persist(xr4 + c1 * CSTRIDE4, pol);
    float4 vi1 = ldg_persist(xi4 + c1 * CSTRIDE4, pol);

#pragma unroll
    for (int k = 0; k < C; k += 2) {
        const int cc0 = (k + rot) & (C - 1);
        const int cc1 = (k + 1 + rot) & (C - 1);
        float4 nr0, ni0, nr1, ni1;
        if (k + 2 < C) {
            const int nc0 = (k + 2 + rot) & (C - 1);
            const int nc1 = (k + 3 + rot) & (C - 1);
            nr0 = ldg_persist(xr4 + nc0 * CSTRIDE4, pol);
            ni0 = ldg_persist(xi4 + nc0 * CSTRIDE4, pol);
            nr1 = ldg_persist(xr4 + nc1 * CSTRIDE4, pol);
            ni1 = ldg_persist(xi4 + nc1 * CSTRIDE4, pol);
        }

        {
            float4 w0 = swr4[cc0 * 2];
            float4 u0 = swi4[cc0 * 2];
            float wv[4] = {w0.x, w0.y, w0.z, w0.w};
            float uv[4] = {u0.x, u0.y, u0.z, u0.w};
#pragma unroll
            for (int f = 0; f < FPT; ++f)
                cplx_fma(ar[f], ai[f], wv[f], uv[f], vr0, vi0);
        }
        {
            float4 w0 = swr4[cc1 * 2];
            float4 u0 = swi4[cc1 * 2];
            float wv[4] = {w0.x, w0.y, w0.z, w0.w};
            float uv[4] = {u0.x, u0.y, u0.z, u0.w};
#pragma unroll
            for (int f = 0; f < FPT; ++f)
                cplx_fma(ar[f], ai[f], wv[f], uv[f], vr1, vi1);
        }

        if (k + 2 < C) {
            vr0 = nr0; vi0 = ni0; vr1 = nr1; vi1 = ni1;
        }
    }

    // out shape (2, B, F, L, M); relu on real part; streaming stores.
    float4* out4 = reinterpret_cast<float4*>(out);
#pragma unroll
    for (int f = 0; f < FPT; ++f) {
        int fglob = fg * FPT + f;
        float4 r = ar[f];
        r.x = fmaxf(r.x, 0.f);
        r.y = fmaxf(r.y, 0.f);
        r.z = fmaxf(r.z, 0.f);
        r.w = fmaxf(r.w, 0.f);
        size_t or4 = (((size_t)(0 * B + b) * F + fglob) * L + l) * (M / 4) + m4;
        size_t oi4 = (((size_t)(1 * B + b) * F + fglob) * L + l) * (M / 4) + m4;
        stg_stream(out4 + or4, r);
        stg_stream(out4 + oi4, ai[f]);
    }
}

}  // namespace

extern "C" void kernel_launch(void* const* d_in, const int* in_sizes, int n_in,
                              void* d_out, int out_size)
{
    const float* xr = (const float*)d_in[0];
    const float* xi = (const float*)d_in[1];
    const float* wr = (const float*)d_in[2];
    const float* wi = (const float*)d_in[3];
    float* out = (float*)d_out;
    sphere_conv_kernel<<<B * L, THREADS>>>(xr, xi, wr, wi, out);
}